// round 12
// baseline (speedup 1.0000x reference)
#include <cuda_runtime.h>
#include <cuda_fp16.h>
#include <math.h>
#include <stdint.h>

#define B_    8
#define S_    4096
#define DIN   512
#define DHID  1024
#define DOUT  512
#define M_    (B_ * S_)          // 32768 rows
#define LCH   128                // scan chunk length
#define NCH   (S_ / LCH)         // 32 chunks

// ---------------------------------------------------------------------------
// Scratch (__device__ globals)
// ---------------------------------------------------------------------------
__device__ float  g_a[DHID];
__device__ float  g_gate[DHID];
__device__ __half g_x16[(size_t)M_ * DIN];
__device__ __half g_u16[(size_t)M_ * DHID];
__device__ __half g_h16[(size_t)M_ * DHID];
__device__ float  g_part[(size_t)B_ * NCH * DHID];
__device__ float  g_carry[(size_t)B_ * NCH * DHID];
__device__ __half g_winT16[DHID * DIN];
__device__ __half g_wdxT16[DOUT * DIN];
__device__ __half g_woutT16[DOUT * DHID];

// ---------------------------------------------------------------------------
// PTX helpers (baseline sm_80+ only)
// ---------------------------------------------------------------------------
__device__ __forceinline__ uint32_t smem_u32(const void* p) {
    uint32_t a;
    asm("{ .reg .u64 t; cvta.to.shared.u64 t, %1; cvt.u32.u64 %0, t; }"
        : "=r"(a) : "l"(p));
    return a;
}
__device__ __forceinline__ void cp_async16(uint32_t saddr, const void* gptr) {
    asm volatile("cp.async.cg.shared.global [%0], [%1], 16;"
                 :: "r"(saddr), "l"(gptr));
}
#define CP_COMMIT() asm volatile("cp.async.commit_group;" ::: "memory")
#define CP_WAIT(n)  asm volatile("cp.async.wait_group %0;" :: "n"(n) : "memory")

__device__ __forceinline__ void ldsm_x4(uint32_t& r0, uint32_t& r1,
                                        uint32_t& r2, uint32_t& r3, uint32_t addr) {
    asm volatile("ldmatrix.sync.aligned.m8n8.x4.shared.b16 {%0,%1,%2,%3}, [%4];"
                 : "=r"(r0), "=r"(r1), "=r"(r2), "=r"(r3) : "r"(addr));
}
__device__ __forceinline__ void mma_16816(float* d, const uint32_t* a,
                                          uint32_t b0, uint32_t b1) {
    asm volatile("mma.sync.aligned.m16n8k16.row.col.f32.f16.f16.f32 "
                 "{%0,%1,%2,%3}, {%4,%5,%6,%7}, {%8,%9}, {%0,%1,%2,%3};"
                 : "+f"(d[0]), "+f"(d[1]), "+f"(d[2]), "+f"(d[3])
                 : "r"(a[0]), "r"(a[1]), "r"(a[2]), "r"(a[3]), "r"(b0), "r"(b1));
}

// ---------------------------------------------------------------------------
// SMEM tiles: 128 rows x 64 halves = 128B/row, XOR swizzle (unit ^= row&7).
// Double-buffered. Two CTA flavors:
//   gemm_u:   128 threads (4 warps), warp tile 64x64   (measured 95.7us)
//   gemm_out: 256 threads (8 warps), warp tile 32x64   (measured ~145us)
// ---------------------------------------------------------------------------
#define ROWB     128
#define TILE_B   (128 * ROWB)         // 16384
#define STAGE_B  (2 * TILE_B)         // A + B tile = 32768
#define SMEM_TOT (2 * STAGE_B)        // 65536

// Generic stage loader: NT = threads in CTA
template<int NT>
__device__ __forceinline__ void load_stage_async(uint32_t s_base,
    const __half* __restrict__ A, int lda, int am0, int ak0,
    const __half* __restrict__ Bm, int ldb, int bn0, int bk0)
{
    const int tid = threadIdx.x;
#pragma unroll
    for (int i = 0; i < 1024 / NT; i++) {
        int id  = tid + i * NT;       // 0..1023
        int row = id >> 3;
        int u   = id & 7;
        int su  = (u ^ (row & 7)) * 16;
        cp_async16(s_base + row * ROWB + su,
                   A + (size_t)(am0 + row) * lda + ak0 + u * 8);
        cp_async16(s_base + TILE_B + row * ROWB + su,
                   Bm + (size_t)(bn0 + row) * ldb + bk0 + u * 8);
    }
}

// Warp tile 64(m) x 64(n): acc[4][8][4]  (gemm_u flavor)
__device__ __forceinline__ void compute_stage64(uint32_t s_base,
    float acc[4][8][4], int warp_m, int warp_n, int lane)
{
    const uint32_t aB = s_base;
    const uint32_t bB = s_base + TILE_B;
#pragma unroll
    for (int ks = 0; ks < 4; ks++) {
        uint32_t a[4][4];
#pragma unroll
        for (int im = 0; im < 4; im++) {
            int row  = warp_m * 64 + im * 16 + (lane & 7) + ((lane >> 3) & 1) * 8;
            int unit = ks * 2 + (lane >> 4);
            ldsm_x4(a[im][0], a[im][1], a[im][2], a[im][3],
                    aB + row * ROWB + ((unit ^ (row & 7)) * 16));
        }
        uint32_t b[4][4];
#pragma unroll
        for (int jn = 0; jn < 4; jn++) {
            int row  = warp_n * 64 + jn * 16 + (lane & 7) + ((lane >> 4) & 1) * 8;
            int unit = ks * 2 + ((lane >> 3) & 1);
            ldsm_x4(b[jn][0], b[jn][1], b[jn][2], b[jn][3],
                    bB + row * ROWB + ((unit ^ (row & 7)) * 16));
        }
#pragma unroll
        for (int im = 0; im < 4; im++)
#pragma unroll
            for (int jn = 0; jn < 4; jn++) {
                mma_16816(acc[im][jn * 2 + 0], a[im], b[jn][0], b[jn][1]);
                mma_16816(acc[im][jn * 2 + 1], a[im], b[jn][2], b[jn][3]);
            }
    }
}

// Warp tile 32(m) x 64(n): acc[2][8][4]  (gemm_out flavor)
__device__ __forceinline__ void compute_stage32(uint32_t s_base,
    float acc[2][8][4], int warp_m, int warp_n, int lane)
{
    const uint32_t aB = s_base;
    const uint32_t bB = s_base + TILE_B;
#pragma unroll
    for (int ks = 0; ks < 4; ks++) {
        uint32_t a[2][4];
#pragma unroll
        for (int im = 0; im < 2; im++) {
            int row  = warp_m * 32 + im * 16 + (lane & 7) + ((lane >> 3) & 1) * 8;
            int unit = ks * 2 + (lane >> 4);
            ldsm_x4(a[im][0], a[im][1], a[im][2], a[im][3],
                    aB + row * ROWB + ((unit ^ (row & 7)) * 16));
        }
        uint32_t b[4][4];
#pragma unroll
        for (int jn = 0; jn < 4; jn++) {
            int row  = warp_n * 64 + jn * 16 + (lane & 7) + ((lane >> 4) & 1) * 8;
            int unit = ks * 2 + ((lane >> 3) & 1);
            ldsm_x4(b[jn][0], b[jn][1], b[jn][2], b[jn][3],
                    bB + row * ROWB + ((unit ^ (row & 7)) * 16));
        }
#pragma unroll
        for (int im = 0; im < 2; im++)
#pragma unroll
            for (int jn = 0; jn < 4; jn++) {
                mma_16816(acc[im][jn * 2 + 0], a[im], b[jn][0], b[jn][1]);
                mma_16816(acc[im][jn * 2 + 1], a[im], b[jn][2], b[jn][3]);
            }
    }
}

// ---------------------------------------------------------------------------
// Fused prep: [0,4): precompute | [4, 8196): convert_x | [8196, 9476): transpose
// ---------------------------------------------------------------------------
__global__ __launch_bounds__(256) void prep_kernel(
    const float* __restrict__ a_logit, const float* __restrict__ x,
    const float* __restrict__ Win, const float* __restrict__ Wdx,
    const float* __restrict__ Wout)
{
    int bid = blockIdx.x;
    if (bid < 4) {
        // precompute a / gate
        int d = bid * 256 + threadIdx.x;
        float a = 1.0f / (1.0f + expf(-a_logit[d]));
        g_a[d] = a;
        g_gate[d] = sqrtf(fmaxf(1.0f - a * a, 0.0f));
        return;
    }
    if (bid < 4 + 8192) {
        // convert x -> fp16
        size_t i = ((size_t)(bid - 4) * 256 + threadIdx.x) * 8;
        float4 v0 = *(const float4*)(x + i);
        float4 v1 = *(const float4*)(x + i + 4);
        *(__half2*)(g_x16 + i + 0) = __floats2half2_rn(v0.x, v0.y);
        *(__half2*)(g_x16 + i + 2) = __floats2half2_rn(v0.z, v0.w);
        *(__half2*)(g_x16 + i + 4) = __floats2half2_rn(v1.x, v1.y);
        *(__half2*)(g_x16 + i + 6) = __floats2half2_rn(v1.z, v1.w);
        return;
    }
    // transpose+convert weights; 256 threads as (32, 8)
    __shared__ float t[32][33];
    int wb = bid - (4 + 8192);    // 0..1279
    const float* W; __half* T; int K, N, nb;
    if (wb < 512)      { W = Win;  T = g_winT16;  K = DIN;  N = DHID; nb = 32; }
    else if (wb < 768) { W = Wdx;  T = g_wdxT16;  K = DIN;  N = DOUT; nb = 16; wb -= 512; }
    else               { W = Wout; T = g_woutT16; K = DHID; N = DOUT; nb = 16; wb -= 768; }
    int n0 = (wb % nb) * 32, k0 = (wb / nb) * 32;
    int tx = threadIdx.x & 31, ty = threadIdx.x >> 5;   // (32, 8)
#pragma unroll
    for (int i = 0; i < 4; i++)
        t[ty + i * 8][tx] = W[(size_t)(k0 + ty + i * 8) * N + n0 + tx];
    __syncthreads();
#pragma unroll
    for (int i = 0; i < 4; i++)
        T[(size_t)(n0 + ty + i * 8) * K + k0 + tx] = __float2half_rn(t[tx][ty + i * 8]);
}

// ---------------------------------------------------------------------------
// GEMM 1 (128 threads, 64x64 warp tile): u = gate*(x@W_in + b_in) -> g_u16
// ---------------------------------------------------------------------------
__global__ __launch_bounds__(128, 2) void gemm_u_mma(const float* __restrict__ bias) {
    extern __shared__ char smem[];
    const uint32_t sb = smem_u32(smem);
    const int tid = threadIdx.x, wid = tid >> 5, lane = tid & 31;
    const int warp_m = wid >> 1, warp_n = wid & 1;
    const int bn = blockIdx.x * 128, bm = blockIdx.y * 128;

    float acc[4][8][4];
#pragma unroll
    for (int i = 0; i < 4; i++)
#pragma unroll
        for (int j = 0; j < 8; j++)
#pragma unroll
            for (int r = 0; r < 4; r++) acc[i][j][r] = 0.0f;

    load_stage_async<128>(sb, g_x16, DIN, bm, 0, g_winT16, DIN, bn, 0);
    CP_COMMIT();

    const int NC = DIN / 64;     // 8
    for (int c = 0; c < NC; c++) {
        uint32_t cur = sb + (c & 1) * STAGE_B;
        if (c + 1 < NC) {
            load_stage_async<128>(sb + ((c + 1) & 1) * STAGE_B,
                                  g_x16, DIN, bm, (c + 1) * 64,
                                  g_winT16, DIN, bn, (c + 1) * 64);
            CP_COMMIT();
            CP_WAIT(1);
        } else {
            CP_WAIT(0);
        }
        __syncthreads();
        compute_stage64(cur, acc, warp_m, warp_n, lane);
        __syncthreads();
    }

    const int rw = lane >> 2, cq = lane & 3;
#pragma unroll
    for (int im = 0; im < 4; im++) {
        int m0 = bm + warp_m * 64 + im * 16 + rw;
#pragma unroll
        for (int jf = 0; jf < 8; jf++) {
            int n = bn + warp_n * 64 + jf * 8 + cq * 2;
            float g0 = g_gate[n], g1 = g_gate[n + 1];
            float b0 = bias[n],   b1 = bias[n + 1];
            float* a4 = acc[im][jf];
            *(__half2*)(g_u16 + (size_t)m0 * DHID + n) =
                __floats2half2_rn(g0 * (a4[0] + b0), g1 * (a4[1] + b1));
            *(__half2*)(g_u16 + (size_t)(m0 + 8) * DHID + n) =
                __floats2half2_rn(g0 * (a4[2] + b0), g1 * (a4[3] + b1));
        }
    }
}

// ---------------------------------------------------------------------------
// Chunked parallel scan
// ---------------------------------------------------------------------------
__global__ __launch_bounds__(256) void scan_phaseA() {
    int d = blockIdx.x * 256 + threadIdx.x;      // 0..1023 (4 blocks)
    int c = blockIdx.y, b = blockIdx.z;
    float a = g_a[d];
    const __half* up = g_u16 + ((size_t)(b * S_ + c * LCH)) * DHID + d;
    float v = 0.0f;
#pragma unroll 8
    for (int t = 0; t < LCH; t++)
        v = fmaf(a, v, __half2float(up[(size_t)t * DHID]));
    g_part[((size_t)b * NCH + c) * DHID + d] = v;
}

// Phase B: batch-load all 32 chunk partials (MLP=32), then serial carry chain.
__global__ __launch_bounds__(256) void scan_phaseB(
    const float* __restrict__ h0, float* __restrict__ out) {
    int idx = blockIdx.x * 256 + threadIdx.x;    // 0..8191
    int b = idx >> 10, d = idx & 1023;
    float a = g_a[d];
    float aL = a;
#pragma unroll
    for (int i = 0; i < 7; i++) aL = aL * aL;    // a^128
    const float* part = g_part + (size_t)b * NCH * DHID + d;
    float* cr = g_carry + (size_t)b * NCH * DHID + d;

    // 1) independent loads — all 32 in flight at once
    float p[NCH];
#pragma unroll
    for (int c = 0; c < NCH; c++) p[c] = part[(size_t)c * DHID];

    // 2) serial carry chain in registers
    float carry = h0[idx];
    float cv[NCH];
#pragma unroll
    for (int c = 0; c < NCH; c++) {
        cv[c] = carry;
        carry = fmaf(aL, carry, p[c]);
    }

    // 3) stores
#pragma unroll
    for (int c = 0; c < NCH; c++) cr[(size_t)c * DHID] = cv[c];
    out[(size_t)M_ * DOUT + idx] = carry;         // h_last
}

__global__ __launch_bounds__(256) void scan_phaseC() {
    int d = blockIdx.x * 256 + threadIdx.x;
    int c = blockIdx.y, b = blockIdx.z;
    float a = g_a[d];
    float h = g_carry[((size_t)b * NCH + c) * DHID + d];
    const __half* up = g_u16 + ((size_t)(b * S_ + c * LCH)) * DHID + d;
    __half* hp = g_h16 + ((size_t)(b * S_ + c * LCH)) * DHID + d;
#pragma unroll 8
    for (int t = 0; t < LCH; t++) {
        h = fmaf(a, h, __half2float(up[(size_t)t * DHID]));
        hp[(size_t)t * DHID] = __float2half_rn(h);
    }
}

// ---------------------------------------------------------------------------
// GEMM 2 (256 threads, 32x64 warp tile): out = 0.5*(x@W_dx + h@W_out + biases)
// ---------------------------------------------------------------------------
__device__ __forceinline__ void load_chunk2(uint32_t s_base, int c, int bm, int bn) {
    if (c < 8)
        load_stage_async<256>(s_base, g_x16, DIN, bm, c * 64,
                              g_wdxT16, DIN, bn, c * 64);
    else
        load_stage_async<256>(s_base, g_h16, DHID, bm, (c - 8) * 64,
                              g_woutT16, DHID, bn, (c - 8) * 64);
}

__global__ __launch_bounds__(256, 2) void gemm_out_mma(
    const float* __restrict__ bdx, const float* __restrict__ bout,
    float* __restrict__ out)
{
    extern __shared__ char smem[];
    const uint32_t sb = smem_u32(smem);
    const int tid = threadIdx.x, wid = tid >> 5, lane = tid & 31;
    const int warp_m = wid >> 1, warp_n = wid & 1;
    const int bn = blockIdx.x * 128, bm = blockIdx.y * 128;

    float acc[2][8][4];
#pragma unroll
    for (int i = 0; i < 2; i++)
#pragma unroll
        for (int j = 0; j < 8; j++)
#pragma unroll
            for (int r = 0; r < 4; r++) acc[i][j][r] = 0.0f;

    load_chunk2(sb, 0, bm, bn);
    CP_COMMIT();

    const int NC = 24;
    for (int c = 0; c < NC; c++) {
        uint32_t cur = sb + (c & 1) * STAGE_B;
        if (c + 1 < NC) {
            load_chunk2(sb + ((c + 1) & 1) * STAGE_B, c + 1, bm, bn);
            CP_COMMIT();
            CP_WAIT(1);
        } else {
            CP_WAIT(0);
        }
        __syncthreads();
        compute_stage32(cur, acc, warp_m, warp_n, lane);
        __syncthreads();
    }

    const int rw = lane >> 2, cq = lane & 3;
#pragma unroll
    for (int im = 0; im < 2; im++) {
        int m0 = bm + warp_m * 32 + im * 16 + rw;
#pragma unroll
        for (int jf = 0; jf < 8; jf++) {
            int n = bn + warp_n * 64 + jf * 8 + cq * 2;
            float b0 = bdx[n] + bout[n], b1 = bdx[n + 1] + bout[n + 1];
            float* a4 = acc[im][jf];
            *(float2*)(out + (size_t)m0 * DOUT + n) =
                make_float2(0.5f * (a4[0] + b0), 0.5f * (a4[1] + b1));
            *(float2*)(out + (size_t)(m0 + 8) * DOUT + n) =
                make_float2(0.5f * (a4[2] + b0), 0.5f * (a4[3] + b1));
        }
    }
}

// ---------------------------------------------------------------------------
extern "C" void kernel_launch(void* const* d_in, const int* in_sizes, int n_in,
                              void* d_out, int out_size)
{
    const float* x       = (const float*)d_in[0];
    const float* h0      = (const float*)d_in[1];
    const float* a_logit = (const float*)d_in[2];
    const float* W_dx    = (const float*)d_in[3];
    const float* b_dx    = (const float*)d_in[4];
    const float* W_in    = (const float*)d_in[5];
    const float* b_in    = (const float*)d_in[6];
    const float* W_out   = (const float*)d_in[7];
    const float* b_out   = (const float*)d_in[8];
    float* out = (float*)d_out;

    cudaFuncSetAttribute(gemm_u_mma,   cudaFuncAttributeMaxDynamicSharedMemorySize, SMEM_TOT);
    cudaFuncSetAttribute(gemm_out_mma, cudaFuncAttributeMaxDynamicSharedMemorySize, SMEM_TOT);

    prep_kernel<<<4 + 8192 + 1280, 256>>>(a_logit, x, W_in, W_dx, W_out);

    gemm_u_mma<<<dim3(DHID / 128, M_ / 128), 128, SMEM_TOT>>>(b_in);

    scan_phaseA<<<dim3(4, NCH, B_), 256>>>();
    scan_phaseB<<<(B_ * DHID) / 256, 256>>>(h0, out);
    scan_phaseC<<<dim3(4, NCH, B_), 256>>>();

    gemm_out_mma<<<dim3(DOUT / 128, M_ / 128), 256, SMEM_TOT>>>(b_dx, b_out, out);
}

// round 13
// speedup vs baseline: 1.4104x; 1.4104x over previous
#include <cuda_runtime.h>
#include <cuda_fp16.h>
#include <math.h>
#include <stdint.h>

#define B_    8
#define S_    4096
#define DIN   512
#define DHID  1024
#define DOUT  512
#define M_    (B_ * S_)          // 32768 rows
#define LCH   128                // scan chunk length
#define NCH   (S_ / LCH)         // 32 chunks

// ---------------------------------------------------------------------------
// Scratch (__device__ globals)
// ---------------------------------------------------------------------------
__device__ float  g_a[DHID];
__device__ float  g_gate[DHID];
__device__ __half g_x16[(size_t)M_ * DIN];
__device__ __half g_u16[(size_t)M_ * DHID];
__device__ __half g_h16[(size_t)M_ * DHID];
__device__ float  g_part[(size_t)B_ * NCH * DHID];
__device__ float  g_carry[(size_t)B_ * NCH * DHID];
__device__ __half g_winT16[DHID * DIN];
__device__ __half g_wdxT16[DOUT * DIN];
__device__ __half g_woutT16[DOUT * DHID];

// ---------------------------------------------------------------------------
// PTX helpers (baseline sm_80+ only)
// ---------------------------------------------------------------------------
__device__ __forceinline__ uint32_t smem_u32(const void* p) {
    uint32_t a;
    asm("{ .reg .u64 t; cvta.to.shared.u64 t, %1; cvt.u32.u64 %0, t; }"
        : "=r"(a) : "l"(p));
    return a;
}
__device__ __forceinline__ void cp_async16(uint32_t saddr, const void* gptr) {
    asm volatile("cp.async.cg.shared.global [%0], [%1], 16;"
                 :: "r"(saddr), "l"(gptr));
}
#define CP_COMMIT() asm volatile("cp.async.commit_group;" ::: "memory")
#define CP_WAIT(n)  asm volatile("cp.async.wait_group %0;" :: "n"(n) : "memory")

__device__ __forceinline__ void ldsm_x4(uint32_t& r0, uint32_t& r1,
                                        uint32_t& r2, uint32_t& r3, uint32_t addr) {
    asm volatile("ldmatrix.sync.aligned.m8n8.x4.shared.b16 {%0,%1,%2,%3}, [%4];"
                 : "=r"(r0), "=r"(r1), "=r"(r2), "=r"(r3) : "r"(addr));
}
__device__ __forceinline__ void mma_16816(float* d, const uint32_t* a,
                                          uint32_t b0, uint32_t b1) {
    asm volatile("mma.sync.aligned.m16n8k16.row.col.f32.f16.f16.f32 "
                 "{%0,%1,%2,%3}, {%4,%5,%6,%7}, {%8,%9}, {%0,%1,%2,%3};"
                 : "+f"(d[0]), "+f"(d[1]), "+f"(d[2]), "+f"(d[3])
                 : "r"(a[0]), "r"(a[1]), "r"(a[2]), "r"(a[3]), "r"(b0), "r"(b1));
}

// ---------------------------------------------------------------------------
// SMEM tiles: 128 rows x 64 halves = 128B/row, XOR swizzle (unit ^= row&7).
// Double-buffered. Two CTA flavors:
//   gemm_u:   128 threads (4 warps), warp tile 64x64   (measured 95.7us)
//   gemm_out: 256 threads (8 warps), warp tile 32x64   (measured ~145us)
// ---------------------------------------------------------------------------
#define ROWB     128
#define TILE_B   (128 * ROWB)         // 16384
#define STAGE_B  (2 * TILE_B)         // A + B tile = 32768
#define SMEM_TOT (2 * STAGE_B)        // 65536

// Generic stage loader: NT = threads in CTA
template<int NT>
__device__ __forceinline__ void load_stage_async(uint32_t s_base,
    const __half* __restrict__ A, int lda, int am0, int ak0,
    const __half* __restrict__ Bm, int ldb, int bn0, int bk0)
{
    const int tid = threadIdx.x;
#pragma unroll
    for (int i = 0; i < 1024 / NT; i++) {
        int id  = tid + i * NT;       // 0..1023
        int row = id >> 3;
        int u   = id & 7;
        int su  = (u ^ (row & 7)) * 16;
        cp_async16(s_base + row * ROWB + su,
                   A + (size_t)(am0 + row) * lda + ak0 + u * 8);
        cp_async16(s_base + TILE_B + row * ROWB + su,
                   Bm + (size_t)(bn0 + row) * ldb + bk0 + u * 8);
    }
}

// Warp tile 64(m) x 64(n): acc[4][8][4]  (gemm_u flavor)
__device__ __forceinline__ void compute_stage64(uint32_t s_base,
    float acc[4][8][4], int warp_m, int warp_n, int lane)
{
    const uint32_t aB = s_base;
    const uint32_t bB = s_base + TILE_B;
#pragma unroll
    for (int ks = 0; ks < 4; ks++) {
        uint32_t a[4][4];
#pragma unroll
        for (int im = 0; im < 4; im++) {
            int row  = warp_m * 64 + im * 16 + (lane & 7) + ((lane >> 3) & 1) * 8;
            int unit = ks * 2 + (lane >> 4);
            ldsm_x4(a[im][0], a[im][1], a[im][2], a[im][3],
                    aB + row * ROWB + ((unit ^ (row & 7)) * 16));
        }
        uint32_t b[4][4];
#pragma unroll
        for (int jn = 0; jn < 4; jn++) {
            int row  = warp_n * 64 + jn * 16 + (lane & 7) + ((lane >> 4) & 1) * 8;
            int unit = ks * 2 + ((lane >> 3) & 1);
            ldsm_x4(b[jn][0], b[jn][1], b[jn][2], b[jn][3],
                    bB + row * ROWB + ((unit ^ (row & 7)) * 16));
        }
#pragma unroll
        for (int im = 0; im < 4; im++)
#pragma unroll
            for (int jn = 0; jn < 4; jn++) {
                mma_16816(acc[im][jn * 2 + 0], a[im], b[jn][0], b[jn][1]);
                mma_16816(acc[im][jn * 2 + 1], a[im], b[jn][2], b[jn][3]);
            }
    }
}

// Warp tile 32(m) x 64(n): acc[2][8][4]  (gemm_out flavor)
__device__ __forceinline__ void compute_stage32(uint32_t s_base,
    float acc[2][8][4], int warp_m, int warp_n, int lane)
{
    const uint32_t aB = s_base;
    const uint32_t bB = s_base + TILE_B;
#pragma unroll
    for (int ks = 0; ks < 4; ks++) {
        uint32_t a[2][4];
#pragma unroll
        for (int im = 0; im < 2; im++) {
            int row  = warp_m * 32 + im * 16 + (lane & 7) + ((lane >> 3) & 1) * 8;
            int unit = ks * 2 + (lane >> 4);
            ldsm_x4(a[im][0], a[im][1], a[im][2], a[im][3],
                    aB + row * ROWB + ((unit ^ (row & 7)) * 16));
        }
        uint32_t b[4][4];
#pragma unroll
        for (int jn = 0; jn < 4; jn++) {
            int row  = warp_n * 64 + jn * 16 + (lane & 7) + ((lane >> 4) & 1) * 8;
            int unit = ks * 2 + ((lane >> 3) & 1);
            ldsm_x4(b[jn][0], b[jn][1], b[jn][2], b[jn][3],
                    bB + row * ROWB + ((unit ^ (row & 7)) * 16));
        }
#pragma unroll
        for (int im = 0; im < 2; im++)
#pragma unroll
            for (int jn = 0; jn < 4; jn++) {
                mma_16816(acc[im][jn * 2 + 0], a[im], b[jn][0], b[jn][1]);
                mma_16816(acc[im][jn * 2 + 1], a[im], b[jn][2], b[jn][3]);
            }
    }
}

// ---------------------------------------------------------------------------
// Fused prep: [0,4): precompute | [4, 8196): convert_x | [8196, 9476): transpose
// ---------------------------------------------------------------------------
__global__ __launch_bounds__(256) void prep_kernel(
    const float* __restrict__ a_logit, const float* __restrict__ x,
    const float* __restrict__ Win, const float* __restrict__ Wdx,
    const float* __restrict__ Wout)
{
    int bid = blockIdx.x;
    if (bid < 4) {
        // precompute a / gate
        int d = bid * 256 + threadIdx.x;
        float a = 1.0f / (1.0f + expf(-a_logit[d]));
        g_a[d] = a;
        g_gate[d] = sqrtf(fmaxf(1.0f - a * a, 0.0f));
        return;
    }
    if (bid < 4 + 8192) {
        // convert x -> fp16
        size_t i = ((size_t)(bid - 4) * 256 + threadIdx.x) * 8;
        float4 v0 = *(const float4*)(x + i);
        float4 v1 = *(const float4*)(x + i + 4);
        *(__half2*)(g_x16 + i + 0) = __floats2half2_rn(v0.x, v0.y);
        *(__half2*)(g_x16 + i + 2) = __floats2half2_rn(v0.z, v0.w);
        *(__half2*)(g_x16 + i + 4) = __floats2half2_rn(v1.x, v1.y);
        *(__half2*)(g_x16 + i + 6) = __floats2half2_rn(v1.z, v1.w);
        return;
    }
    // transpose+convert weights; 256 threads as (32, 8)
    __shared__ float t[32][33];
    int wb = bid - (4 + 8192);    // 0..1279
    const float* W; __half* T; int K, N, nb;
    if (wb < 512)      { W = Win;  T = g_winT16;  K = DIN;  N = DHID; nb = 32; }
    else if (wb < 768) { W = Wdx;  T = g_wdxT16;  K = DIN;  N = DOUT; nb = 16; wb -= 512; }
    else               { W = Wout; T = g_woutT16; K = DHID; N = DOUT; nb = 16; wb -= 768; }
    int n0 = (wb % nb) * 32, k0 = (wb / nb) * 32;
    int tx = threadIdx.x & 31, ty = threadIdx.x >> 5;   // (32, 8)
#pragma unroll
    for (int i = 0; i < 4; i++)
        t[ty + i * 8][tx] = W[(size_t)(k0 + ty + i * 8) * N + n0 + tx];
    __syncthreads();
#pragma unroll
    for (int i = 0; i < 4; i++)
        T[(size_t)(n0 + ty + i * 8) * K + k0 + tx] = __float2half_rn(t[tx][ty + i * 8]);
}

// ---------------------------------------------------------------------------
// GEMM 1 (128 threads, 64x64 warp tile): u = gate*(x@W_in + b_in) -> g_u16
// ---------------------------------------------------------------------------
__global__ __launch_bounds__(128, 2) void gemm_u_mma(const float* __restrict__ bias) {
    extern __shared__ char smem[];
    const uint32_t sb = smem_u32(smem);
    const int tid = threadIdx.x, wid = tid >> 5, lane = tid & 31;
    const int warp_m = wid >> 1, warp_n = wid & 1;
    const int bn = blockIdx.x * 128, bm = blockIdx.y * 128;

    float acc[4][8][4];
#pragma unroll
    for (int i = 0; i < 4; i++)
#pragma unroll
        for (int j = 0; j < 8; j++)
#pragma unroll
            for (int r = 0; r < 4; r++) acc[i][j][r] = 0.0f;

    load_stage_async<128>(sb, g_x16, DIN, bm, 0, g_winT16, DIN, bn, 0);
    CP_COMMIT();

    const int NC = DIN / 64;     // 8
    for (int c = 0; c < NC; c++) {
        uint32_t cur = sb + (c & 1) * STAGE_B;
        if (c + 1 < NC) {
            load_stage_async<128>(sb + ((c + 1) & 1) * STAGE_B,
                                  g_x16, DIN, bm, (c + 1) * 64,
                                  g_winT16, DIN, bn, (c + 1) * 64);
            CP_COMMIT();
            CP_WAIT(1);
        } else {
            CP_WAIT(0);
        }
        __syncthreads();
        compute_stage64(cur, acc, warp_m, warp_n, lane);
        __syncthreads();
    }

    const int rw = lane >> 2, cq = lane & 3;
#pragma unroll
    for (int im = 0; im < 4; im++) {
        int m0 = bm + warp_m * 64 + im * 16 + rw;
#pragma unroll
        for (int jf = 0; jf < 8; jf++) {
            int n = bn + warp_n * 64 + jf * 8 + cq * 2;
            float g0 = g_gate[n], g1 = g_gate[n + 1];
            float b0 = bias[n],   b1 = bias[n + 1];
            float* a4 = acc[im][jf];
            *(__half2*)(g_u16 + (size_t)m0 * DHID + n) =
                __floats2half2_rn(g0 * (a4[0] + b0), g1 * (a4[1] + b1));
            *(__half2*)(g_u16 + (size_t)(m0 + 8) * DHID + n) =
                __floats2half2_rn(g0 * (a4[2] + b0), g1 * (a4[3] + b1));
        }
    }
}

// ---------------------------------------------------------------------------
// Chunked parallel scan
// ---------------------------------------------------------------------------
__global__ __launch_bounds__(256) void scan_phaseA() {
    int d = blockIdx.x * 256 + threadIdx.x;      // 0..1023 (4 blocks)
    int c = blockIdx.y, b = blockIdx.z;
    float a = g_a[d];
    const __half* up = g_u16 + ((size_t)(b * S_ + c * LCH)) * DHID + d;
    float v = 0.0f;
#pragma unroll 8
    for (int t = 0; t < LCH; t++)
        v = fmaf(a, v, __half2float(up[(size_t)t * DHID]));
    g_part[((size_t)b * NCH + c) * DHID + d] = v;
}

// Phase B: batch-load all 32 chunk partials (MLP=32), then serial carry chain.
__global__ __launch_bounds__(256) void scan_phaseB(
    const float* __restrict__ h0, float* __restrict__ out) {
    int idx = blockIdx.x * 256 + threadIdx.x;    // 0..8191
    int b = idx >> 10, d = idx & 1023;
    float a = g_a[d];
    float aL = a;
#pragma unroll
    for (int i = 0; i < 7; i++) aL = aL * aL;    // a^128
    const float* part = g_part + (size_t)b * NCH * DHID + d;
    float* cr = g_carry + (size_t)b * NCH * DHID + d;

    // 1) independent loads — all 32 in flight at once
    float p[NCH];
#pragma unroll
    for (int c = 0; c < NCH; c++) p[c] = part[(size_t)c * DHID];

    // 2) serial carry chain in registers
    float carry = h0[idx];
    float cv[NCH];
#pragma unroll
    for (int c = 0; c < NCH; c++) {
        cv[c] = carry;
        carry = fmaf(aL, carry, p[c]);
    }

    // 3) stores
#pragma unroll
    for (int c = 0; c < NCH; c++) cr[(size_t)c * DHID] = cv[c];
    out[(size_t)M_ * DOUT + idx] = carry;         // h_last
}

__global__ __launch_bounds__(256) void scan_phaseC() {
    int d = blockIdx.x * 256 + threadIdx.x;
    int c = blockIdx.y, b = blockIdx.z;
    float a = g_a[d];
    float h = g_carry[((size_t)b * NCH + c) * DHID + d];
    const __half* up = g_u16 + ((size_t)(b * S_ + c * LCH)) * DHID + d;
    __half* hp = g_h16 + ((size_t)(b * S_ + c * LCH)) * DHID + d;
#pragma unroll 8
    for (int t = 0; t < LCH; t++) {
        h = fmaf(a, h, __half2float(up[(size_t)t * DHID]));
        hp[(size_t)t * DHID] = __float2half_rn(h);
    }
}

// ---------------------------------------------------------------------------
// GEMM 2 (256 threads, 32x64 warp tile): out = 0.5*(x@W_dx + h@W_out + biases)
// ---------------------------------------------------------------------------
__device__ __forceinline__ void load_chunk2(uint32_t s_base, int c, int bm, int bn) {
    if (c < 8)
        load_stage_async<256>(s_base, g_x16, DIN, bm, c * 64,
                              g_wdxT16, DIN, bn, c * 64);
    else
        load_stage_async<256>(s_base, g_h16, DHID, bm, (c - 8) * 64,
                              g_woutT16, DHID, bn, (c - 8) * 64);
}

__global__ __launch_bounds__(256, 2) void gemm_out_mma(
    const float* __restrict__ bdx, const float* __restrict__ bout,
    float* __restrict__ out)
{
    extern __shared__ char smem[];
    const uint32_t sb = smem_u32(smem);
    const int tid = threadIdx.x, wid = tid >> 5, lane = tid & 31;
    const int warp_m = wid >> 1, warp_n = wid & 1;
    const int bn = blockIdx.x * 128, bm = blockIdx.y * 128;

    float acc[2][8][4];
#pragma unroll
    for (int i = 0; i < 2; i++)
#pragma unroll
        for (int j = 0; j < 8; j++)
#pragma unroll
            for (int r = 0; r < 4; r++) acc[i][j][r] = 0.0f;

    load_chunk2(sb, 0, bm, bn);
    CP_COMMIT();

    const int NC = 24;
    for (int c = 0; c < NC; c++) {
        uint32_t cur = sb + (c & 1) * STAGE_B;
        if (c + 1 < NC) {
            load_chunk2(sb + ((c + 1) & 1) * STAGE_B, c + 1, bm, bn);
            CP_COMMIT();
            CP_WAIT(1);
        } else {
            CP_WAIT(0);
        }
        __syncthreads();
        compute_stage32(cur, acc, warp_m, warp_n, lane);
        __syncthreads();
    }

    const int rw = lane >> 2, cq = lane & 3;
#pragma unroll
    for (int im = 0; im < 2; im++) {
        int m0 = bm + warp_m * 32 + im * 16 + rw;
#pragma unroll
        for (int jf = 0; jf < 8; jf++) {
            int n = bn + warp_n * 64 + jf * 8 + cq * 2;
            float b0 = bdx[n] + bout[n], b1 = bdx[n + 1] + bout[n + 1];
            float* a4 = acc[im][jf];
            *(float2*)(out + (size_t)m0 * DOUT + n) =
                make_float2(0.5f * (a4[0] + b0), 0.5f * (a4[1] + b1));
            *(float2*)(out + (size_t)(m0 + 8) * DOUT + n) =
                make_float2(0.5f * (a4[2] + b0), 0.5f * (a4[3] + b1));
        }
    }
}

// ---------------------------------------------------------------------------
extern "C" void kernel_launch(void* const* d_in, const int* in_sizes, int n_in,
                              void* d_out, int out_size)
{
    const float* x       = (const float*)d_in[0];
    const float* h0      = (const float*)d_in[1];
    const float* a_logit = (const float*)d_in[2];
    const float* W_dx    = (const float*)d_in[3];
    const float* b_dx    = (const float*)d_in[4];
    const float* W_in    = (const float*)d_in[5];
    const float* b_in    = (const float*)d_in[6];
    const float* W_out   = (const float*)d_in[7];
    const float* b_out   = (const float*)d_in[8];
    float* out = (float*)d_out;

    cudaFuncSetAttribute(gemm_u_mma,   cudaFuncAttributeMaxDynamicSharedMemorySize, SMEM_TOT);
    cudaFuncSetAttribute(gemm_out_mma, cudaFuncAttributeMaxDynamicSharedMemorySize, SMEM_TOT);

    prep_kernel<<<4 + 8192 + 1280, 256>>>(a_logit, x, W_in, W_dx, W_out);

    gemm_u_mma<<<dim3(DHID / 128, M_ / 128), 128, SMEM_TOT>>>(b_in);

    scan_phaseA<<<dim3(4, NCH, B_), 256>>>();
    scan_phaseB<<<(B_ * DHID) / 256, 256>>>(h0, out);
    scan_phaseC<<<dim3(4, NCH, B_), 256>>>();

    gemm_out_mma<<<dim3(DOUT / 128, M_ / 128), 256, SMEM_TOT>>>(b_dx, b_out, out);
}

// round 14
// speedup vs baseline: 1.4433x; 1.0234x over previous
#include <cuda_runtime.h>
#include <cuda_fp16.h>
#include <math.h>
#include <stdint.h>

#define B_    8
#define S_    4096
#define DIN   512
#define DHID  1024
#define DOUT  512
#define M_    (B_ * S_)          // 32768 rows
#define LCH   128                // scan chunk length
#define NCH   (S_ / LCH)         // 32 chunks

// ---------------------------------------------------------------------------
// Scratch (__device__ globals)
// ---------------------------------------------------------------------------
__device__ float  g_a[DHID];
__device__ float  g_gate[DHID];
__device__ __half g_x16[(size_t)M_ * DIN];
__device__ __half g_u16[(size_t)M_ * DHID];
__device__ __half g_h16[(size_t)M_ * DHID];
__device__ float  g_part[(size_t)B_ * NCH * DHID];
__device__ __half g_winT16[DHID * DIN];
__device__ __half g_wdxT16[DOUT * DIN];
__device__ __half g_woutT16[DOUT * DHID];

// ---------------------------------------------------------------------------
// PTX helpers (baseline sm_80+ only)
// ---------------------------------------------------------------------------
__device__ __forceinline__ uint32_t smem_u32(const void* p) {
    uint32_t a;
    asm("{ .reg .u64 t; cvta.to.shared.u64 t, %1; cvt.u32.u64 %0, t; }"
        : "=r"(a) : "l"(p));
    return a;
}
__device__ __forceinline__ void cp_async16(uint32_t saddr, const void* gptr) {
    asm volatile("cp.async.cg.shared.global [%0], [%1], 16;"
                 :: "r"(saddr), "l"(gptr));
}
#define CP_COMMIT() asm volatile("cp.async.commit_group;" ::: "memory")
#define CP_WAIT(n)  asm volatile("cp.async.wait_group %0;" :: "n"(n) : "memory")

__device__ __forceinline__ void ldsm_x4(uint32_t& r0, uint32_t& r1,
                                        uint32_t& r2, uint32_t& r3, uint32_t addr) {
    asm volatile("ldmatrix.sync.aligned.m8n8.x4.shared.b16 {%0,%1,%2,%3}, [%4];"
                 : "=r"(r0), "=r"(r1), "=r"(r2), "=r"(r3) : "r"(addr));
}
__device__ __forceinline__ void mma_16816(float* d, const uint32_t* a,
                                          uint32_t b0, uint32_t b1) {
    asm volatile("mma.sync.aligned.m16n8k16.row.col.f32.f16.f16.f32 "
                 "{%0,%1,%2,%3}, {%4,%5,%6,%7}, {%8,%9}, {%0,%1,%2,%3};"
                 : "+f"(d[0]), "+f"(d[1]), "+f"(d[2]), "+f"(d[3])
                 : "r"(a[0]), "r"(a[1]), "r"(a[2]), "r"(a[3]), "r"(b0), "r"(b1));
}

// ---------------------------------------------------------------------------
// SMEM tiles: 128 rows x 64 halves = 128B/row, XOR swizzle (unit ^= row&7).
// Double-buffered. Two CTA flavors:
//   gemm_u:   128 threads (4 warps), warp tile 64x64   (measured 95.7us)
//   gemm_out: 256 threads (8 warps), warp tile 32x64   (measured ~145us)
// ---------------------------------------------------------------------------
#define ROWB     128
#define TILE_B   (128 * ROWB)         // 16384
#define STAGE_B  (2 * TILE_B)         // A + B tile = 32768
#define SMEM_TOT (2 * STAGE_B)        // 65536

// Generic stage loader: NT = threads in CTA
template<int NT>
__device__ __forceinline__ void load_stage_async(uint32_t s_base,
    const __half* __restrict__ A, int lda, int am0, int ak0,
    const __half* __restrict__ Bm, int ldb, int bn0, int bk0)
{
    const int tid = threadIdx.x;
#pragma unroll
    for (int i = 0; i < 1024 / NT; i++) {
        int id  = tid + i * NT;       // 0..1023
        int row = id >> 3;
        int u   = id & 7;
        int su  = (u ^ (row & 7)) * 16;
        cp_async16(s_base + row * ROWB + su,
                   A + (size_t)(am0 + row) * lda + ak0 + u * 8);
        cp_async16(s_base + TILE_B + row * ROWB + su,
                   Bm + (size_t)(bn0 + row) * ldb + bk0 + u * 8);
    }
}

// Warp tile 64(m) x 64(n): acc[4][8][4]  (gemm_u flavor)
__device__ __forceinline__ void compute_stage64(uint32_t s_base,
    float acc[4][8][4], int warp_m, int warp_n, int lane)
{
    const uint32_t aB = s_base;
    const uint32_t bB = s_base + TILE_B;
#pragma unroll
    for (int ks = 0; ks < 4; ks++) {
        uint32_t a[4][4];
#pragma unroll
        for (int im = 0; im < 4; im++) {
            int row  = warp_m * 64 + im * 16 + (lane & 7) + ((lane >> 3) & 1) * 8;
            int unit = ks * 2 + (lane >> 4);
            ldsm_x4(a[im][0], a[im][1], a[im][2], a[im][3],
                    aB + row * ROWB + ((unit ^ (row & 7)) * 16));
        }
        uint32_t b[4][4];
#pragma unroll
        for (int jn = 0; jn < 4; jn++) {
            int row  = warp_n * 64 + jn * 16 + (lane & 7) + ((lane >> 4) & 1) * 8;
            int unit = ks * 2 + ((lane >> 3) & 1);
            ldsm_x4(b[jn][0], b[jn][1], b[jn][2], b[jn][3],
                    bB + row * ROWB + ((unit ^ (row & 7)) * 16));
        }
#pragma unroll
        for (int im = 0; im < 4; im++)
#pragma unroll
            for (int jn = 0; jn < 4; jn++) {
                mma_16816(acc[im][jn * 2 + 0], a[im], b[jn][0], b[jn][1]);
                mma_16816(acc[im][jn * 2 + 1], a[im], b[jn][2], b[jn][3]);
            }
    }
}

// Warp tile 32(m) x 64(n): acc[2][8][4]  (gemm_out flavor)
__device__ __forceinline__ void compute_stage32(uint32_t s_base,
    float acc[2][8][4], int warp_m, int warp_n, int lane)
{
    const uint32_t aB = s_base;
    const uint32_t bB = s_base + TILE_B;
#pragma unroll
    for (int ks = 0; ks < 4; ks++) {
        uint32_t a[2][4];
#pragma unroll
        for (int im = 0; im < 2; im++) {
            int row  = warp_m * 32 + im * 16 + (lane & 7) + ((lane >> 3) & 1) * 8;
            int unit = ks * 2 + (lane >> 4);
            ldsm_x4(a[im][0], a[im][1], a[im][2], a[im][3],
                    aB + row * ROWB + ((unit ^ (row & 7)) * 16));
        }
        uint32_t b[4][4];
#pragma unroll
        for (int jn = 0; jn < 4; jn++) {
            int row  = warp_n * 64 + jn * 16 + (lane & 7) + ((lane >> 4) & 1) * 8;
            int unit = ks * 2 + ((lane >> 3) & 1);
            ldsm_x4(b[jn][0], b[jn][1], b[jn][2], b[jn][3],
                    bB + row * ROWB + ((unit ^ (row & 7)) * 16));
        }
#pragma unroll
        for (int im = 0; im < 2; im++)
#pragma unroll
            for (int jn = 0; jn < 4; jn++) {
                mma_16816(acc[im][jn * 2 + 0], a[im], b[jn][0], b[jn][1]);
                mma_16816(acc[im][jn * 2 + 1], a[im], b[jn][2], b[jn][3]);
            }
    }
}

// ---------------------------------------------------------------------------
// Fused prep: [0,4): precompute | [4, 8196): convert_x | [8196, 9476): transpose
// ---------------------------------------------------------------------------
__global__ __launch_bounds__(256) void prep_kernel(
    const float* __restrict__ a_logit, const float* __restrict__ x,
    const float* __restrict__ Win, const float* __restrict__ Wdx,
    const float* __restrict__ Wout)
{
    int bid = blockIdx.x;
    if (bid < 4) {
        // precompute a / gate
        int d = bid * 256 + threadIdx.x;
        float a = 1.0f / (1.0f + expf(-a_logit[d]));
        g_a[d] = a;
        g_gate[d] = sqrtf(fmaxf(1.0f - a * a, 0.0f));
        return;
    }
    if (bid < 4 + 8192) {
        // convert x -> fp16
        size_t i = ((size_t)(bid - 4) * 256 + threadIdx.x) * 8;
        float4 v0 = *(const float4*)(x + i);
        float4 v1 = *(const float4*)(x + i + 4);
        *(__half2*)(g_x16 + i + 0) = __floats2half2_rn(v0.x, v0.y);
        *(__half2*)(g_x16 + i + 2) = __floats2half2_rn(v0.z, v0.w);
        *(__half2*)(g_x16 + i + 4) = __floats2half2_rn(v1.x, v1.y);
        *(__half2*)(g_x16 + i + 6) = __floats2half2_rn(v1.z, v1.w);
        return;
    }
    // transpose+convert weights; 256 threads as (32, 8)
    __shared__ float t[32][33];
    int wb = bid - (4 + 8192);    // 0..1279
    const float* W; __half* T; int K, N, nb;
    if (wb < 512)      { W = Win;  T = g_winT16;  K = DIN;  N = DHID; nb = 32; }
    else if (wb < 768) { W = Wdx;  T = g_wdxT16;  K = DIN;  N = DOUT; nb = 16; wb -= 512; }
    else               { W = Wout; T = g_woutT16; K = DHID; N = DOUT; nb = 16; wb -= 768; }
    int n0 = (wb % nb) * 32, k0 = (wb / nb) * 32;
    int tx = threadIdx.x & 31, ty = threadIdx.x >> 5;   // (32, 8)
#pragma unroll
    for (int i = 0; i < 4; i++)
        t[ty + i * 8][tx] = W[(size_t)(k0 + ty + i * 8) * N + n0 + tx];
    __syncthreads();
#pragma unroll
    for (int i = 0; i < 4; i++)
        T[(size_t)(n0 + ty + i * 8) * K + k0 + tx] = __float2half_rn(t[tx][ty + i * 8]);
}

// ---------------------------------------------------------------------------
// GEMM 1 (128 threads, 64x64 warp tile): u = gate*(x@W_in + b_in) -> g_u16
// ---------------------------------------------------------------------------
__global__ __launch_bounds__(128, 2) void gemm_u_mma(const float* __restrict__ bias) {
    extern __shared__ char smem[];
    const uint32_t sb = smem_u32(smem);
    const int tid = threadIdx.x, wid = tid >> 5, lane = tid & 31;
    const int warp_m = wid >> 1, warp_n = wid & 1;
    const int bn = blockIdx.x * 128, bm = blockIdx.y * 128;

    float acc[4][8][4];
#pragma unroll
    for (int i = 0; i < 4; i++)
#pragma unroll
        for (int j = 0; j < 8; j++)
#pragma unroll
            for (int r = 0; r < 4; r++) acc[i][j][r] = 0.0f;

    load_stage_async<128>(sb, g_x16, DIN, bm, 0, g_winT16, DIN, bn, 0);
    CP_COMMIT();

    const int NC = DIN / 64;     // 8
    for (int c = 0; c < NC; c++) {
        uint32_t cur = sb + (c & 1) * STAGE_B;
        if (c + 1 < NC) {
            load_stage_async<128>(sb + ((c + 1) & 1) * STAGE_B,
                                  g_x16, DIN, bm, (c + 1) * 64,
                                  g_winT16, DIN, bn, (c + 1) * 64);
            CP_COMMIT();
            CP_WAIT(1);
        } else {
            CP_WAIT(0);
        }
        __syncthreads();
        compute_stage64(cur, acc, warp_m, warp_n, lane);
        __syncthreads();
    }

    const int rw = lane >> 2, cq = lane & 3;
#pragma unroll
    for (int im = 0; im < 4; im++) {
        int m0 = bm + warp_m * 64 + im * 16 + rw;
#pragma unroll
        for (int jf = 0; jf < 8; jf++) {
            int n = bn + warp_n * 64 + jf * 8 + cq * 2;
            float g0 = g_gate[n], g1 = g_gate[n + 1];
            float b0 = bias[n],   b1 = bias[n + 1];
            float* a4 = acc[im][jf];
            *(__half2*)(g_u16 + (size_t)m0 * DHID + n) =
                __floats2half2_rn(g0 * (a4[0] + b0), g1 * (a4[1] + b1));
            *(__half2*)(g_u16 + (size_t)(m0 + 8) * DHID + n) =
                __floats2half2_rn(g0 * (a4[2] + b0), g1 * (a4[3] + b1));
        }
    }
}

// ---------------------------------------------------------------------------
// Chunked parallel scan (phase B folded into phase C via redundant carries)
// ---------------------------------------------------------------------------
__global__ __launch_bounds__(256) void scan_phaseA() {
    int d = blockIdx.x * 256 + threadIdx.x;      // 0..1023 (4 blocks)
    int c = blockIdx.y, b = blockIdx.z;
    float a = g_a[d];
    const __half* up = g_u16 + ((size_t)(b * S_ + c * LCH)) * DHID + d;
    float v = 0.0f;
#pragma unroll 8
    for (int t = 0; t < LCH; t++)
        v = fmaf(a, v, __half2float(up[(size_t)t * DHID]));
    g_part[((size_t)b * NCH + c) * DHID + d] = v;
}

// Phase C': each (b,c,d) thread derives its own carry from h0 + parts[0..c-1]
// (batched loads, predicated fmafs), then scans its chunk and writes h (fp16).
// The c == NCH-1 thread's final value IS h_last -> out tail.
__global__ __launch_bounds__(256) void scan_phaseC(
    const float* __restrict__ h0, float* __restrict__ out) {
    int d = blockIdx.x * 256 + threadIdx.x;
    int c = blockIdx.y, b = blockIdx.z;
    float a = g_a[d];
    float aL = a;
#pragma unroll
    for (int i = 0; i < 7; i++) aL = aL * aL;    // a^128

    // carry_c = fold of h0 and parts[0..c-1] with decay aL
    const float* part = g_part + (size_t)b * NCH * DHID + d;
    float p[NCH];
#pragma unroll
    for (int j = 0; j < NCH; j++) p[j] = part[(size_t)j * DHID];   // MLP=32
    float h = h0[b * DHID + d];
#pragma unroll
    for (int j = 0; j < NCH; j++)
        if (j < c) h = fmaf(aL, h, p[j]);

    // serial scan of this chunk from the carry
    const __half* up = g_u16 + ((size_t)(b * S_ + c * LCH)) * DHID + d;
    __half* hp = g_h16 + ((size_t)(b * S_ + c * LCH)) * DHID + d;
#pragma unroll 8
    for (int t = 0; t < LCH; t++) {
        h = fmaf(a, h, __half2float(up[(size_t)t * DHID]));
        hp[(size_t)t * DHID] = __float2half_rn(h);
    }
    if (c == NCH - 1)
        out[(size_t)M_ * DOUT + b * DHID + d] = h;   // h_last
}

// ---------------------------------------------------------------------------
// GEMM 2 (256 threads, 32x64 warp tile): out = 0.5*(x@W_dx + h@W_out + biases)
// ---------------------------------------------------------------------------
__device__ __forceinline__ void load_chunk2(uint32_t s_base, int c, int bm, int bn) {
    if (c < 8)
        load_stage_async<256>(s_base, g_x16, DIN, bm, c * 64,
                              g_wdxT16, DIN, bn, c * 64);
    else
        load_stage_async<256>(s_base, g_h16, DHID, bm, (c - 8) * 64,
                              g_woutT16, DHID, bn, (c - 8) * 64);
}

__global__ __launch_bounds__(256, 2) void gemm_out_mma(
    const float* __restrict__ bdx, const float* __restrict__ bout,
    float* __restrict__ out)
{
    extern __shared__ char smem[];
    const uint32_t sb = smem_u32(smem);
    const int tid = threadIdx.x, wid = tid >> 5, lane = tid & 31;
    const int warp_m = wid >> 1, warp_n = wid & 1;
    const int bn = blockIdx.x * 128, bm = blockIdx.y * 128;

    float acc[2][8][4];
#pragma unroll
    for (int i = 0; i < 2; i++)
#pragma unroll
        for (int j = 0; j < 8; j++)
#pragma unroll
            for (int r = 0; r < 4; r++) acc[i][j][r] = 0.0f;

    load_chunk2(sb, 0, bm, bn);
    CP_COMMIT();

    const int NC = 24;
    for (int c = 0; c < NC; c++) {
        uint32_t cur = sb + (c & 1) * STAGE_B;
        if (c + 1 < NC) {
            load_chunk2(sb + ((c + 1) & 1) * STAGE_B, c + 1, bm, bn);
            CP_COMMIT();
            CP_WAIT(1);
        } else {
            CP_WAIT(0);
        }
        __syncthreads();
        compute_stage32(cur, acc, warp_m, warp_n, lane);
        __syncthreads();
    }

    const int rw = lane >> 2, cq = lane & 3;
#pragma unroll
    for (int im = 0; im < 2; im++) {
        int m0 = bm + warp_m * 32 + im * 16 + rw;
#pragma unroll
        for (int jf = 0; jf < 8; jf++) {
            int n = bn + warp_n * 64 + jf * 8 + cq * 2;
            float b0 = bdx[n] + bout[n], b1 = bdx[n + 1] + bout[n + 1];
            float* a4 = acc[im][jf];
            *(float2*)(out + (size_t)m0 * DOUT + n) =
                make_float2(0.5f * (a4[0] + b0), 0.5f * (a4[1] + b1));
            *(float2*)(out + (size_t)(m0 + 8) * DOUT + n) =
                make_float2(0.5f * (a4[2] + b0), 0.5f * (a4[3] + b1));
        }
    }
}

// ---------------------------------------------------------------------------
extern "C" void kernel_launch(void* const* d_in, const int* in_sizes, int n_in,
                              void* d_out, int out_size)
{
    const float* x       = (const float*)d_in[0];
    const float* h0      = (const float*)d_in[1];
    const float* a_logit = (const float*)d_in[2];
    const float* W_dx    = (const float*)d_in[3];
    const float* b_dx    = (const float*)d_in[4];
    const float* W_in    = (const float*)d_in[5];
    const float* b_in    = (const float*)d_in[6];
    const float* W_out   = (const float*)d_in[7];
    const float* b_out   = (const float*)d_in[8];
    float* out = (float*)d_out;

    cudaFuncSetAttribute(gemm_u_mma,   cudaFuncAttributeMaxDynamicSharedMemorySize, SMEM_TOT);
    cudaFuncSetAttribute(gemm_out_mma, cudaFuncAttributeMaxDynamicSharedMemorySize, SMEM_TOT);

    prep_kernel<<<4 + 8192 + 1280, 256>>>(a_logit, x, W_in, W_dx, W_out);

    gemm_u_mma<<<dim3(DHID / 128, M_ / 128), 128, SMEM_TOT>>>(b_in);

    scan_phaseA<<<dim3(4, NCH, B_), 256>>>();
    scan_phaseC<<<dim3(4, NCH, B_), 256>>>(h0, out);

    gemm_out_mma<<<dim3(DOUT / 128, M_ / 128), 256, SMEM_TOT>>>(b_dx, b_out, out);
}

// round 15
// speedup vs baseline: 1.4450x; 1.0011x over previous
#include <cuda_runtime.h>
#include <cuda_fp16.h>
#include <math.h>
#include <stdint.h>

#define B_    8
#define S_    4096
#define DIN   512
#define DHID  1024
#define DOUT  512
#define M_    (B_ * S_)          // 32768 rows
#define LCH   128                // scan chunk length
#define NCH   (S_ / LCH)         // 32 chunks

// ---------------------------------------------------------------------------
// Scratch (__device__ globals)
// ---------------------------------------------------------------------------
__device__ float  g_a[DHID];
__device__ float  g_gate[DHID];
__device__ __half g_x16[(size_t)M_ * DIN];
__device__ __half g_u16[(size_t)M_ * DHID];
__device__ __half g_h16[(size_t)M_ * DHID];
__device__ float  g_part[(size_t)B_ * NCH * DHID];
__device__ __half g_winT16[DHID * DIN];
__device__ __half g_wdxT16[DOUT * DIN];
__device__ __half g_woutT16[DOUT * DHID];

// ---------------------------------------------------------------------------
// PTX helpers (baseline sm_80+ only)
// ---------------------------------------------------------------------------
__device__ __forceinline__ uint32_t smem_u32(const void* p) {
    uint32_t a;
    asm("{ .reg .u64 t; cvta.to.shared.u64 t, %1; cvt.u32.u64 %0, t; }"
        : "=r"(a) : "l"(p));
    return a;
}
__device__ __forceinline__ void cp_async16(uint32_t saddr, const void* gptr) {
    asm volatile("cp.async.cg.shared.global [%0], [%1], 16;"
                 :: "r"(saddr), "l"(gptr));
}
#define CP_COMMIT() asm volatile("cp.async.commit_group;" ::: "memory")
#define CP_WAIT(n)  asm volatile("cp.async.wait_group %0;" :: "n"(n) : "memory")

__device__ __forceinline__ void ldsm_x4(uint32_t& r0, uint32_t& r1,
                                        uint32_t& r2, uint32_t& r3, uint32_t addr) {
    asm volatile("ldmatrix.sync.aligned.m8n8.x4.shared.b16 {%0,%1,%2,%3}, [%4];"
                 : "=r"(r0), "=r"(r1), "=r"(r2), "=r"(r3) : "r"(addr));
}
__device__ __forceinline__ void mma_16816(float* d, const uint32_t* a,
                                          uint32_t b0, uint32_t b1) {
    asm volatile("mma.sync.aligned.m16n8k16.row.col.f32.f16.f16.f32 "
                 "{%0,%1,%2,%3}, {%4,%5,%6,%7}, {%8,%9}, {%0,%1,%2,%3};"
                 : "+f"(d[0]), "+f"(d[1]), "+f"(d[2]), "+f"(d[3])
                 : "r"(a[0]), "r"(a[1]), "r"(a[2]), "r"(a[3]), "r"(b0), "r"(b1));
}

// ---------------------------------------------------------------------------
// SMEM tiles: 128 rows x 64 halves = 128B/row, XOR swizzle (unit ^= row&7).
// Double-buffered. Two CTA flavors:
//   gemm_u:   128 threads (4 warps), warp tile 64x64   (measured 95.7us)
//   gemm_out: 256 threads (8 warps), warp tile 32x64   (measured ~145us)
// ---------------------------------------------------------------------------
#define ROWB     128
#define TILE_B   (128 * ROWB)         // 16384
#define STAGE_B  (2 * TILE_B)         // A + B tile = 32768
#define SMEM_TOT (2 * STAGE_B)        // 65536

// Generic stage loader: NT = threads in CTA
template<int NT>
__device__ __forceinline__ void load_stage_async(uint32_t s_base,
    const __half* __restrict__ A, int lda, int am0, int ak0,
    const __half* __restrict__ Bm, int ldb, int bn0, int bk0)
{
    const int tid = threadIdx.x;
#pragma unroll
    for (int i = 0; i < 1024 / NT; i++) {
        int id  = tid + i * NT;       // 0..1023
        int row = id >> 3;
        int u   = id & 7;
        int su  = (u ^ (row & 7)) * 16;
        cp_async16(s_base + row * ROWB + su,
                   A + (size_t)(am0 + row) * lda + ak0 + u * 8);
        cp_async16(s_base + TILE_B + row * ROWB + su,
                   Bm + (size_t)(bn0 + row) * ldb + bk0 + u * 8);
    }
}

// Warp tile 64(m) x 64(n): acc[4][8][4]  (gemm_u flavor)
__device__ __forceinline__ void compute_stage64(uint32_t s_base,
    float acc[4][8][4], int warp_m, int warp_n, int lane)
{
    const uint32_t aB = s_base;
    const uint32_t bB = s_base + TILE_B;
#pragma unroll
    for (int ks = 0; ks < 4; ks++) {
        uint32_t a[4][4];
#pragma unroll
        for (int im = 0; im < 4; im++) {
            int row  = warp_m * 64 + im * 16 + (lane & 7) + ((lane >> 3) & 1) * 8;
            int unit = ks * 2 + (lane >> 4);
            ldsm_x4(a[im][0], a[im][1], a[im][2], a[im][3],
                    aB + row * ROWB + ((unit ^ (row & 7)) * 16));
        }
        uint32_t b[4][4];
#pragma unroll
        for (int jn = 0; jn < 4; jn++) {
            int row  = warp_n * 64 + jn * 16 + (lane & 7) + ((lane >> 4) & 1) * 8;
            int unit = ks * 2 + ((lane >> 3) & 1);
            ldsm_x4(b[jn][0], b[jn][1], b[jn][2], b[jn][3],
                    bB + row * ROWB + ((unit ^ (row & 7)) * 16));
        }
#pragma unroll
        for (int im = 0; im < 4; im++)
#pragma unroll
            for (int jn = 0; jn < 4; jn++) {
                mma_16816(acc[im][jn * 2 + 0], a[im], b[jn][0], b[jn][1]);
                mma_16816(acc[im][jn * 2 + 1], a[im], b[jn][2], b[jn][3]);
            }
    }
}

// Warp tile 32(m) x 64(n): acc[2][8][4]  (gemm_out flavor)
__device__ __forceinline__ void compute_stage32(uint32_t s_base,
    float acc[2][8][4], int warp_m, int warp_n, int lane)
{
    const uint32_t aB = s_base;
    const uint32_t bB = s_base + TILE_B;
#pragma unroll
    for (int ks = 0; ks < 4; ks++) {
        uint32_t a[2][4];
#pragma unroll
        for (int im = 0; im < 2; im++) {
            int row  = warp_m * 32 + im * 16 + (lane & 7) + ((lane >> 3) & 1) * 8;
            int unit = ks * 2 + (lane >> 4);
            ldsm_x4(a[im][0], a[im][1], a[im][2], a[im][3],
                    aB + row * ROWB + ((unit ^ (row & 7)) * 16));
        }
        uint32_t b[4][4];
#pragma unroll
        for (int jn = 0; jn < 4; jn++) {
            int row  = warp_n * 64 + jn * 16 + (lane & 7) + ((lane >> 4) & 1) * 8;
            int unit = ks * 2 + ((lane >> 3) & 1);
            ldsm_x4(b[jn][0], b[jn][1], b[jn][2], b[jn][3],
                    bB + row * ROWB + ((unit ^ (row & 7)) * 16));
        }
#pragma unroll
        for (int im = 0; im < 2; im++)
#pragma unroll
            for (int jn = 0; jn < 4; jn++) {
                mma_16816(acc[im][jn * 2 + 0], a[im], b[jn][0], b[jn][1]);
                mma_16816(acc[im][jn * 2 + 1], a[im], b[jn][2], b[jn][3]);
            }
    }
}

// ---------------------------------------------------------------------------
// Fused prep: [0,4): precompute | [4, 8196): convert_x | [8196, 9476): transpose
// ---------------------------------------------------------------------------
__global__ __launch_bounds__(256) void prep_kernel(
    const float* __restrict__ a_logit, const float* __restrict__ x,
    const float* __restrict__ Win, const float* __restrict__ Wdx,
    const float* __restrict__ Wout)
{
    int bid = blockIdx.x;
    if (bid < 4) {
        // precompute a / gate
        int d = bid * 256 + threadIdx.x;
        float a = 1.0f / (1.0f + expf(-a_logit[d]));
        g_a[d] = a;
        g_gate[d] = sqrtf(fmaxf(1.0f - a * a, 0.0f));
        return;
    }
    if (bid < 4 + 8192) {
        // convert x -> fp16
        size_t i = ((size_t)(bid - 4) * 256 + threadIdx.x) * 8;
        float4 v0 = *(const float4*)(x + i);
        float4 v1 = *(const float4*)(x + i + 4);
        *(__half2*)(g_x16 + i + 0) = __floats2half2_rn(v0.x, v0.y);
        *(__half2*)(g_x16 + i + 2) = __floats2half2_rn(v0.z, v0.w);
        *(__half2*)(g_x16 + i + 4) = __floats2half2_rn(v1.x, v1.y);
        *(__half2*)(g_x16 + i + 6) = __floats2half2_rn(v1.z, v1.w);
        return;
    }
    // transpose+convert weights; 256 threads as (32, 8)
    __shared__ float t[32][33];
    int wb = bid - (4 + 8192);    // 0..1279
    const float* W; __half* T; int K, N, nb;
    if (wb < 512)      { W = Win;  T = g_winT16;  K = DIN;  N = DHID; nb = 32; }
    else if (wb < 768) { W = Wdx;  T = g_wdxT16;  K = DIN;  N = DOUT; nb = 16; wb -= 512; }
    else               { W = Wout; T = g_woutT16; K = DHID; N = DOUT; nb = 16; wb -= 768; }
    int n0 = (wb % nb) * 32, k0 = (wb / nb) * 32;
    int tx = threadIdx.x & 31, ty = threadIdx.x >> 5;   // (32, 8)
#pragma unroll
    for (int i = 0; i < 4; i++)
        t[ty + i * 8][tx] = W[(size_t)(k0 + ty + i * 8) * N + n0 + tx];
    __syncthreads();
#pragma unroll
    for (int i = 0; i < 4; i++)
        T[(size_t)(n0 + ty + i * 8) * K + k0 + tx] = __float2half_rn(t[tx][ty + i * 8]);
}

// ---------------------------------------------------------------------------
// GEMM 1 (128 threads, 64x64 warp tile): u = gate*(x@W_in + b_in) -> g_u16
// ---------------------------------------------------------------------------
__global__ __launch_bounds__(128, 2) void gemm_u_mma(const float* __restrict__ bias) {
    extern __shared__ char smem[];
    const uint32_t sb = smem_u32(smem);
    const int tid = threadIdx.x, wid = tid >> 5, lane = tid & 31;
    const int warp_m = wid >> 1, warp_n = wid & 1;
    const int bn = blockIdx.x * 128, bm = blockIdx.y * 128;

    float acc[4][8][4];
#pragma unroll
    for (int i = 0; i < 4; i++)
#pragma unroll
        for (int j = 0; j < 8; j++)
#pragma unroll
            for (int r = 0; r < 4; r++) acc[i][j][r] = 0.0f;

    load_stage_async<128>(sb, g_x16, DIN, bm, 0, g_winT16, DIN, bn, 0);
    CP_COMMIT();

    const int NC = DIN / 64;     // 8
    for (int c = 0; c < NC; c++) {
        uint32_t cur = sb + (c & 1) * STAGE_B;
        if (c + 1 < NC) {
            load_stage_async<128>(sb + ((c + 1) & 1) * STAGE_B,
                                  g_x16, DIN, bm, (c + 1) * 64,
                                  g_winT16, DIN, bn, (c + 1) * 64);
            CP_COMMIT();
            CP_WAIT(1);
        } else {
            CP_WAIT(0);
        }
        __syncthreads();
        compute_stage64(cur, acc, warp_m, warp_n, lane);
        __syncthreads();
    }

    const int rw = lane >> 2, cq = lane & 3;
#pragma unroll
    for (int im = 0; im < 4; im++) {
        int m0 = bm + warp_m * 64 + im * 16 + rw;
#pragma unroll
        for (int jf = 0; jf < 8; jf++) {
            int n = bn + warp_n * 64 + jf * 8 + cq * 2;
            float g0 = g_gate[n], g1 = g_gate[n + 1];
            float b0 = bias[n],   b1 = bias[n + 1];
            float* a4 = acc[im][jf];
            *(__half2*)(g_u16 + (size_t)m0 * DHID + n) =
                __floats2half2_rn(g0 * (a4[0] + b0), g1 * (a4[1] + b1));
            *(__half2*)(g_u16 + (size_t)(m0 + 8) * DHID + n) =
                __floats2half2_rn(g0 * (a4[2] + b0), g1 * (a4[3] + b1));
        }
    }
}

// ---------------------------------------------------------------------------
// Chunked parallel scan, half2-vectorized (2 channels per thread)
// ---------------------------------------------------------------------------
__global__ __launch_bounds__(256) void scan_phaseA() {
    int d2 = blockIdx.x * 256 + threadIdx.x;     // 0..511 (2 blocks)
    int d  = d2 * 2;
    int c = blockIdx.y, b = blockIdx.z;
    float2 a = *(const float2*)(g_a + d);
    const __half2* up = (const __half2*)(g_u16 + ((size_t)(b * S_ + c * LCH)) * DHID + d);
    float va = 0.0f, vb = 0.0f;
#pragma unroll 8
    for (int t = 0; t < LCH; t++) {
        float2 u = __half22float2(up[(size_t)t * (DHID / 2)]);
        va = fmaf(a.x, va, u.x);
        vb = fmaf(a.y, vb, u.y);
    }
    *(float2*)(g_part + ((size_t)b * NCH + c) * DHID + d) = make_float2(va, vb);
}

// Phase C': each (b,c,d2) thread derives carries for channels d,d+1 from
// h0 + parts[0..c-1] (batched float2 loads, predicated fmafs), then scans its
// chunk and writes h (half2). The c == NCH-1 values ARE h_last -> out tail.
__global__ __launch_bounds__(256) void scan_phaseC(
    const float* __restrict__ h0, float* __restrict__ out) {
    int d2 = blockIdx.x * 256 + threadIdx.x;     // 0..511 (2 blocks)
    int d  = d2 * 2;
    int c = blockIdx.y, b = blockIdx.z;
    float2 a = *(const float2*)(g_a + d);
    float aLx = a.x, aLy = a.y;
#pragma unroll
    for (int i = 0; i < 7; i++) { aLx *= aLx; aLy *= aLy; }   // a^128

    // carry = fold of h0 and parts[0..c-1] with decay a^128
    const float* part = g_part + (size_t)b * NCH * DHID + d;
    float2 p[NCH];
#pragma unroll
    for (int j = 0; j < NCH; j++) p[j] = *(const float2*)(part + (size_t)j * DHID);
    float2 h = *(const float2*)(h0 + b * DHID + d);
#pragma unroll
    for (int j = 0; j < NCH; j++)
        if (j < c) { h.x = fmaf(aLx, h.x, p[j].x); h.y = fmaf(aLy, h.y, p[j].y); }

    // serial scan of this chunk from the carry (2 channels interleaved)
    const __half2* up = (const __half2*)(g_u16 + ((size_t)(b * S_ + c * LCH)) * DHID + d);
    __half2* hp = (__half2*)(g_h16 + ((size_t)(b * S_ + c * LCH)) * DHID + d);
#pragma unroll 8
    for (int t = 0; t < LCH; t++) {
        float2 u = __half22float2(up[(size_t)t * (DHID / 2)]);
        h.x = fmaf(a.x, h.x, u.x);
        h.y = fmaf(a.y, h.y, u.y);
        hp[(size_t)t * (DHID / 2)] = __floats2half2_rn(h.x, h.y);
    }
    if (c == NCH - 1)
        *(float2*)(out + (size_t)M_ * DOUT + b * DHID + d) = h;   // h_last
}

// ---------------------------------------------------------------------------
// GEMM 2 (256 threads, 32x64 warp tile): out = 0.5*(x@W_dx + h@W_out + biases)
// ---------------------------------------------------------------------------
__device__ __forceinline__ void load_chunk2(uint32_t s_base, int c, int bm, int bn) {
    if (c < 8)
        load_stage_async<256>(s_base, g_x16, DIN, bm, c * 64,
                              g_wdxT16, DIN, bn, c * 64);
    else
        load_stage_async<256>(s_base, g_h16, DHID, bm, (c - 8) * 64,
                              g_woutT16, DHID, bn, (c - 8) * 64);
}

__global__ __launch_bounds__(256, 2) void gemm_out_mma(
    const float* __restrict__ bdx, const float* __restrict__ bout,
    float* __restrict__ out)
{
    extern __shared__ char smem[];
    const uint32_t sb = smem_u32(smem);
    const int tid = threadIdx.x, wid = tid >> 5, lane = tid & 31;
    const int warp_m = wid >> 1, warp_n = wid & 1;
    const int bn = blockIdx.x * 128, bm = blockIdx.y * 128;

    float acc[2][8][4];
#pragma unroll
    for (int i = 0; i < 2; i++)
#pragma unroll
        for (int j = 0; j < 8; j++)
#pragma unroll
            for (int r = 0; r < 4; r++) acc[i][j][r] = 0.0f;

    load_chunk2(sb, 0, bm, bn);
    CP_COMMIT();

    const int NC = 24;
    for (int c = 0; c < NC; c++) {
        uint32_t cur = sb + (c & 1) * STAGE_B;
        if (c + 1 < NC) {
            load_chunk2(sb + ((c + 1) & 1) * STAGE_B, c + 1, bm, bn);
            CP_COMMIT();
            CP_WAIT(1);
        } else {
            CP_WAIT(0);
        }
        __syncthreads();
        compute_stage32(cur, acc, warp_m, warp_n, lane);
        __syncthreads();
    }

    const int rw = lane >> 2, cq = lane & 3;
#pragma unroll
    for (int im = 0; im < 2; im++) {
        int m0 = bm + warp_m * 32 + im * 16 + rw;
#pragma unroll
        for (int jf = 0; jf < 8; jf++) {
            int n = bn + warp_n * 64 + jf * 8 + cq * 2;
            float b0 = bdx[n] + bout[n], b1 = bdx[n + 1] + bout[n + 1];
            float* a4 = acc[im][jf];
            *(float2*)(out + (size_t)m0 * DOUT + n) =
                make_float2(0.5f * (a4[0] + b0), 0.5f * (a4[1] + b1));
            *(float2*)(out + (size_t)(m0 + 8) * DOUT + n) =
                make_float2(0.5f * (a4[2] + b0), 0.5f * (a4[3] + b1));
        }
    }
}

// ---------------------------------------------------------------------------
extern "C" void kernel_launch(void* const* d_in, const int* in_sizes, int n_in,
                              void* d_out, int out_size)
{
    const float* x       = (const float*)d_in[0];
    const float* h0      = (const float*)d_in[1];
    const float* a_logit = (const float*)d_in[2];
    const float* W_dx    = (const float*)d_in[3];
    const float* b_dx    = (const float*)d_in[4];
    const float* W_in    = (const float*)d_in[5];
    const float* b_in    = (const float*)d_in[6];
    const float* W_out   = (const float*)d_in[7];
    const float* b_out   = (const float*)d_in[8];
    float* out = (float*)d_out;

    cudaFuncSetAttribute(gemm_u_mma,   cudaFuncAttributeMaxDynamicSharedMemorySize, SMEM_TOT);
    cudaFuncSetAttribute(gemm_out_mma, cudaFuncAttributeMaxDynamicSharedMemorySize, SMEM_TOT);

    prep_kernel<<<4 + 8192 + 1280, 256>>>(a_logit, x, W_in, W_dx, W_out);

    gemm_u_mma<<<dim3(DHID / 128, M_ / 128), 128, SMEM_TOT>>>(b_in);

    scan_phaseA<<<dim3(2, NCH, B_), 256>>>();
    scan_phaseC<<<dim3(2, NCH, B_), 256>>>(h0, out);

    gemm_out_mma<<<dim3(DOUT / 128, M_ / 128), 256, SMEM_TOT>>>(b_dx, b_out, out);
}

// round 16
// speedup vs baseline: 1.6860x; 1.1668x over previous
#include <cuda_runtime.h>
#include <cuda_fp16.h>
#include <math.h>
#include <stdint.h>

#define B_    8
#define S_    4096
#define DIN   512
#define DHID  1024
#define DOUT  512
#define M_    (B_ * S_)          // 32768 rows
#define LCH   128                // scan chunk length
#define NCH   (S_ / LCH)         // 32 chunks
#define PF    8                  // scan prefetch depth

// ---------------------------------------------------------------------------
// Scratch (__device__ globals)
// ---------------------------------------------------------------------------
__device__ float  g_a[DHID];
__device__ float  g_gate[DHID];
__device__ __half g_x16[(size_t)M_ * DIN];
__device__ __half g_u16[(size_t)M_ * DHID];
__device__ __half g_h16[(size_t)M_ * DHID];
__device__ float  g_part[(size_t)B_ * NCH * DHID];
__device__ __half g_winT16[DHID * DIN];
__device__ __half g_wdxT16[DOUT * DIN];
__device__ __half g_woutT16[DOUT * DHID];

// ---------------------------------------------------------------------------
// PTX helpers (baseline sm_80+ only)
// ---------------------------------------------------------------------------
__device__ __forceinline__ uint32_t smem_u32(const void* p) {
    uint32_t a;
    asm("{ .reg .u64 t; cvta.to.shared.u64 t, %1; cvt.u32.u64 %0, t; }"
        : "=r"(a) : "l"(p));
    return a;
}
__device__ __forceinline__ void cp_async16(uint32_t saddr, const void* gptr) {
    asm volatile("cp.async.cg.shared.global [%0], [%1], 16;"
                 :: "r"(saddr), "l"(gptr));
}
#define CP_COMMIT() asm volatile("cp.async.commit_group;" ::: "memory")
#define CP_WAIT(n)  asm volatile("cp.async.wait_group %0;" :: "n"(n) : "memory")

__device__ __forceinline__ void ldsm_x4(uint32_t& r0, uint32_t& r1,
                                        uint32_t& r2, uint32_t& r3, uint32_t addr) {
    asm volatile("ldmatrix.sync.aligned.m8n8.x4.shared.b16 {%0,%1,%2,%3}, [%4];"
                 : "=r"(r0), "=r"(r1), "=r"(r2), "=r"(r3) : "r"(addr));
}
__device__ __forceinline__ void mma_16816(float* d, const uint32_t* a,
                                          uint32_t b0, uint32_t b1) {
    asm volatile("mma.sync.aligned.m16n8k16.row.col.f32.f16.f16.f32 "
                 "{%0,%1,%2,%3}, {%4,%5,%6,%7}, {%8,%9}, {%0,%1,%2,%3};"
                 : "+f"(d[0]), "+f"(d[1]), "+f"(d[2]), "+f"(d[3])
                 : "r"(a[0]), "r"(a[1]), "r"(a[2]), "r"(a[3]), "r"(b0), "r"(b1));
}

// ---------------------------------------------------------------------------
// SMEM tiles: 128 rows x 64 halves = 128B/row, XOR swizzle (unit ^= row&7).
// Double-buffered. Two CTA flavors:
//   gemm_u:   128 threads (4 warps), warp tile 64x64   (measured 95.7us)
//   gemm_out: 256 threads (8 warps), warp tile 32x64   (measured ~145us)
// ---------------------------------------------------------------------------
#define ROWB     128
#define TILE_B   (128 * ROWB)         // 16384
#define STAGE_B  (2 * TILE_B)         // A + B tile = 32768
#define SMEM_TOT (2 * STAGE_B)        // 65536

// Generic stage loader: NT = threads in CTA
template<int NT>
__device__ __forceinline__ void load_stage_async(uint32_t s_base,
    const __half* __restrict__ A, int lda, int am0, int ak0,
    const __half* __restrict__ Bm, int ldb, int bn0, int bk0)
{
    const int tid = threadIdx.x;
#pragma unroll
    for (int i = 0; i < 1024 / NT; i++) {
        int id  = tid + i * NT;       // 0..1023
        int row = id >> 3;
        int u   = id & 7;
        int su  = (u ^ (row & 7)) * 16;
        cp_async16(s_base + row * ROWB + su,
                   A + (size_t)(am0 + row) * lda + ak0 + u * 8);
        cp_async16(s_base + TILE_B + row * ROWB + su,
                   Bm + (size_t)(bn0 + row) * ldb + bk0 + u * 8);
    }
}

// Warp tile 64(m) x 64(n): acc[4][8][4]  (gemm_u flavor)
__device__ __forceinline__ void compute_stage64(uint32_t s_base,
    float acc[4][8][4], int warp_m, int warp_n, int lane)
{
    const uint32_t aB = s_base;
    const uint32_t bB = s_base + TILE_B;
#pragma unroll
    for (int ks = 0; ks < 4; ks++) {
        uint32_t a[4][4];
#pragma unroll
        for (int im = 0; im < 4; im++) {
            int row  = warp_m * 64 + im * 16 + (lane & 7) + ((lane >> 3) & 1) * 8;
            int unit = ks * 2 + (lane >> 4);
            ldsm_x4(a[im][0], a[im][1], a[im][2], a[im][3],
                    aB + row * ROWB + ((unit ^ (row & 7)) * 16));
        }
        uint32_t b[4][4];
#pragma unroll
        for (int jn = 0; jn < 4; jn++) {
            int row  = warp_n * 64 + jn * 16 + (lane & 7) + ((lane >> 4) & 1) * 8;
            int unit = ks * 2 + ((lane >> 3) & 1);
            ldsm_x4(b[jn][0], b[jn][1], b[jn][2], b[jn][3],
                    bB + row * ROWB + ((unit ^ (row & 7)) * 16));
        }
#pragma unroll
        for (int im = 0; im < 4; im++)
#pragma unroll
            for (int jn = 0; jn < 4; jn++) {
                mma_16816(acc[im][jn * 2 + 0], a[im], b[jn][0], b[jn][1]);
                mma_16816(acc[im][jn * 2 + 1], a[im], b[jn][2], b[jn][3]);
            }
    }
}

// Warp tile 32(m) x 64(n): acc[2][8][4]  (gemm_out flavor)
__device__ __forceinline__ void compute_stage32(uint32_t s_base,
    float acc[2][8][4], int warp_m, int warp_n, int lane)
{
    const uint32_t aB = s_base;
    const uint32_t bB = s_base + TILE_B;
#pragma unroll
    for (int ks = 0; ks < 4; ks++) {
        uint32_t a[2][4];
#pragma unroll
        for (int im = 0; im < 2; im++) {
            int row  = warp_m * 32 + im * 16 + (lane & 7) + ((lane >> 3) & 1) * 8;
            int unit = ks * 2 + (lane >> 4);
            ldsm_x4(a[im][0], a[im][1], a[im][2], a[im][3],
                    aB + row * ROWB + ((unit ^ (row & 7)) * 16));
        }
        uint32_t b[4][4];
#pragma unroll
        for (int jn = 0; jn < 4; jn++) {
            int row  = warp_n * 64 + jn * 16 + (lane & 7) + ((lane >> 4) & 1) * 8;
            int unit = ks * 2 + ((lane >> 3) & 1);
            ldsm_x4(b[jn][0], b[jn][1], b[jn][2], b[jn][3],
                    bB + row * ROWB + ((unit ^ (row & 7)) * 16));
        }
#pragma unroll
        for (int im = 0; im < 2; im++)
#pragma unroll
            for (int jn = 0; jn < 4; jn++) {
                mma_16816(acc[im][jn * 2 + 0], a[im], b[jn][0], b[jn][1]);
                mma_16816(acc[im][jn * 2 + 1], a[im], b[jn][2], b[jn][3]);
            }
    }
}

// ---------------------------------------------------------------------------
// Fused prep: [0,4): precompute | [4, 8196): convert_x | [8196, 9476): transpose
// ---------------------------------------------------------------------------
__global__ __launch_bounds__(256) void prep_kernel(
    const float* __restrict__ a_logit, const float* __restrict__ x,
    const float* __restrict__ Win, const float* __restrict__ Wdx,
    const float* __restrict__ Wout)
{
    int bid = blockIdx.x;
    if (bid < 4) {
        // precompute a / gate
        int d = bid * 256 + threadIdx.x;
        float a = 1.0f / (1.0f + expf(-a_logit[d]));
        g_a[d] = a;
        g_gate[d] = sqrtf(fmaxf(1.0f - a * a, 0.0f));
        return;
    }
    if (bid < 4 + 8192) {
        // convert x -> fp16
        size_t i = ((size_t)(bid - 4) * 256 + threadIdx.x) * 8;
        float4 v0 = *(const float4*)(x + i);
        float4 v1 = *(const float4*)(x + i + 4);
        *(__half2*)(g_x16 + i + 0) = __floats2half2_rn(v0.x, v0.y);
        *(__half2*)(g_x16 + i + 2) = __floats2half2_rn(v0.z, v0.w);
        *(__half2*)(g_x16 + i + 4) = __floats2half2_rn(v1.x, v1.y);
        *(__half2*)(g_x16 + i + 6) = __floats2half2_rn(v1.z, v1.w);
        return;
    }
    // transpose+convert weights; 256 threads as (32, 8)
    __shared__ float t[32][33];
    int wb = bid - (4 + 8192);    // 0..1279
    const float* W; __half* T; int K, N, nb;
    if (wb < 512)      { W = Win;  T = g_winT16;  K = DIN;  N = DHID; nb = 32; }
    else if (wb < 768) { W = Wdx;  T = g_wdxT16;  K = DIN;  N = DOUT; nb = 16; wb -= 512; }
    else               { W = Wout; T = g_woutT16; K = DHID; N = DOUT; nb = 16; wb -= 768; }
    int n0 = (wb % nb) * 32, k0 = (wb / nb) * 32;
    int tx = threadIdx.x & 31, ty = threadIdx.x >> 5;   // (32, 8)
#pragma unroll
    for (int i = 0; i < 4; i++)
        t[ty + i * 8][tx] = W[(size_t)(k0 + ty + i * 8) * N + n0 + tx];
    __syncthreads();
#pragma unroll
    for (int i = 0; i < 4; i++)
        T[(size_t)(n0 + ty + i * 8) * K + k0 + tx] = __float2half_rn(t[tx][ty + i * 8]);
}

// ---------------------------------------------------------------------------
// GEMM 1 (128 threads, 64x64 warp tile): u = gate*(x@W_in + b_in) -> g_u16
// ---------------------------------------------------------------------------
__global__ __launch_bounds__(128, 2) void gemm_u_mma(const float* __restrict__ bias) {
    extern __shared__ char smem[];
    const uint32_t sb = smem_u32(smem);
    const int tid = threadIdx.x, wid = tid >> 5, lane = tid & 31;
    const int warp_m = wid >> 1, warp_n = wid & 1;
    const int bn = blockIdx.x * 128, bm = blockIdx.y * 128;

    float acc[4][8][4];
#pragma unroll
    for (int i = 0; i < 4; i++)
#pragma unroll
        for (int j = 0; j < 8; j++)
#pragma unroll
            for (int r = 0; r < 4; r++) acc[i][j][r] = 0.0f;

    load_stage_async<128>(sb, g_x16, DIN, bm, 0, g_winT16, DIN, bn, 0);
    CP_COMMIT();

    const int NC = DIN / 64;     // 8
    for (int c = 0; c < NC; c++) {
        uint32_t cur = sb + (c & 1) * STAGE_B;
        if (c + 1 < NC) {
            load_stage_async<128>(sb + ((c + 1) & 1) * STAGE_B,
                                  g_x16, DIN, bm, (c + 1) * 64,
                                  g_winT16, DIN, bn, (c + 1) * 64);
            CP_COMMIT();
            CP_WAIT(1);
        } else {
            CP_WAIT(0);
        }
        __syncthreads();
        compute_stage64(cur, acc, warp_m, warp_n, lane);
        __syncthreads();
    }

    const int rw = lane >> 2, cq = lane & 3;
#pragma unroll
    for (int im = 0; im < 4; im++) {
        int m0 = bm + warp_m * 64 + im * 16 + rw;
#pragma unroll
        for (int jf = 0; jf < 8; jf++) {
            int n = bn + warp_n * 64 + jf * 8 + cq * 2;
            float g0 = g_gate[n], g1 = g_gate[n + 1];
            float b0 = bias[n],   b1 = bias[n + 1];
            float* a4 = acc[im][jf];
            *(__half2*)(g_u16 + (size_t)m0 * DHID + n) =
                __floats2half2_rn(g0 * (a4[0] + b0), g1 * (a4[1] + b1));
            *(__half2*)(g_u16 + (size_t)(m0 + 8) * DHID + n) =
                __floats2half2_rn(g0 * (a4[2] + b0), g1 * (a4[3] + b1));
        }
    }
}

// ---------------------------------------------------------------------------
// Chunked parallel scan, half2 + explicit software-pipelined prefetch
// ---------------------------------------------------------------------------
__global__ __launch_bounds__(256) void scan_phaseA() {
    int d2 = blockIdx.x * 256 + threadIdx.x;     // 0..511 (2 blocks)
    int d  = d2 * 2;
    int c = blockIdx.y, b = blockIdx.z;
    float2 a = *(const float2*)(g_a + d);
    const __half2* up = (const __half2*)(g_u16 + ((size_t)(b * S_ + c * LCH)) * DHID + d);

    __half2 buf[PF];
#pragma unroll
    for (int i = 0; i < PF; i++) buf[i] = up[(size_t)i * (DHID / 2)];

    float va = 0.0f, vb = 0.0f;
#pragma unroll
    for (int tb = 0; tb < LCH; tb += PF) {
        __half2 nbuf[PF];
        if (tb + PF < LCH) {
#pragma unroll
            for (int i = 0; i < PF; i++)
                nbuf[i] = up[(size_t)(tb + PF + i) * (DHID / 2)];
        }
#pragma unroll
        for (int i = 0; i < PF; i++) {
            float2 u = __half22float2(buf[i]);
            va = fmaf(a.x, va, u.x);
            vb = fmaf(a.y, vb, u.y);
        }
#pragma unroll
        for (int i = 0; i < PF; i++) buf[i] = nbuf[i];
    }
    *(float2*)(g_part + ((size_t)b * NCH + c) * DHID + d) = make_float2(va, vb);
}

// Phase C': derive carry from h0 + parts[0..c-1], then prefetch-pipelined
// chunk scan writing h (half2). c == NCH-1 values are h_last -> out tail.
__global__ __launch_bounds__(256) void scan_phaseC(
    const float* __restrict__ h0, float* __restrict__ out) {
    int d2 = blockIdx.x * 256 + threadIdx.x;     // 0..511 (2 blocks)
    int d  = d2 * 2;
    int c = blockIdx.y, b = blockIdx.z;
    float2 a = *(const float2*)(g_a + d);
    float aLx = a.x, aLy = a.y;
#pragma unroll
    for (int i = 0; i < 7; i++) { aLx *= aLx; aLy *= aLy; }   // a^128

    // carry = fold of h0 and parts[0..c-1] with decay a^128
    const float* part = g_part + (size_t)b * NCH * DHID + d;
    float2 p[NCH];
#pragma unroll
    for (int j = 0; j < NCH; j++) p[j] = *(const float2*)(part + (size_t)j * DHID);
    float2 h = *(const float2*)(h0 + b * DHID + d);
#pragma unroll
    for (int j = 0; j < NCH; j++)
        if (j < c) { h.x = fmaf(aLx, h.x, p[j].x); h.y = fmaf(aLy, h.y, p[j].y); }

    // prefetch-pipelined serial scan of this chunk
    const __half2* up = (const __half2*)(g_u16 + ((size_t)(b * S_ + c * LCH)) * DHID + d);
    __half2* hp = (__half2*)(g_h16 + ((size_t)(b * S_ + c * LCH)) * DHID + d);

    __half2 buf[PF];
#pragma unroll
    for (int i = 0; i < PF; i++) buf[i] = up[(size_t)i * (DHID / 2)];

#pragma unroll
    for (int tb = 0; tb < LCH; tb += PF) {
        __half2 nbuf[PF];
        if (tb + PF < LCH) {
#pragma unroll
            for (int i = 0; i < PF; i++)
                nbuf[i] = up[(size_t)(tb + PF + i) * (DHID / 2)];
        }
#pragma unroll
        for (int i = 0; i < PF; i++) {
            float2 u = __half22float2(buf[i]);
            h.x = fmaf(a.x, h.x, u.x);
            h.y = fmaf(a.y, h.y, u.y);
            hp[(size_t)(tb + i) * (DHID / 2)] = __floats2half2_rn(h.x, h.y);
        }
#pragma unroll
        for (int i = 0; i < PF; i++) buf[i] = nbuf[i];
    }
    if (c == NCH - 1)
        *(float2*)(out + (size_t)M_ * DOUT + b * DHID + d) = h;   // h_last
}

// ---------------------------------------------------------------------------
// GEMM 2 (256 threads, 32x64 warp tile): out = 0.5*(x@W_dx + h@W_out + biases)
// ---------------------------------------------------------------------------
__device__ __forceinline__ void load_chunk2(uint32_t s_base, int c, int bm, int bn) {
    if (c < 8)
        load_stage_async<256>(s_base, g_x16, DIN, bm, c * 64,
                              g_wdxT16, DIN, bn, c * 64);
    else
        load_stage_async<256>(s_base, g_h16, DHID, bm, (c - 8) * 64,
                              g_woutT16, DHID, bn, (c - 8) * 64);
}

__global__ __launch_bounds__(256, 2) void gemm_out_mma(
    const float* __restrict__ bdx, const float* __restrict__ bout,
    float* __restrict__ out)
{
    extern __shared__ char smem[];
    const uint32_t sb = smem_u32(smem);
    const int tid = threadIdx.x, wid = tid >> 5, lane = tid & 31;
    const int warp_m = wid >> 1, warp_n = wid & 1;
    const int bn = blockIdx.x * 128, bm = blockIdx.y * 128;

    float acc[2][8][4];
#pragma unroll
    for (int i = 0; i < 2; i++)
#pragma unroll
        for (int j = 0; j < 8; j++)
#pragma unroll
            for (int r = 0; r < 4; r++) acc[i][j][r] = 0.0f;

    load_chunk2(sb, 0, bm, bn);
    CP_COMMIT();

    const int NC = 24;
    for (int c = 0; c < NC; c++) {
        uint32_t cur = sb + (c & 1) * STAGE_B;
        if (c + 1 < NC) {
            load_chunk2(sb + ((c + 1) & 1) * STAGE_B, c + 1, bm, bn);
            CP_COMMIT();
            CP_WAIT(1);
        } else {
            CP_WAIT(0);
        }
        __syncthreads();
        compute_stage32(cur, acc, warp_m, warp_n, lane);
        __syncthreads();
    }

    const int rw = lane >> 2, cq = lane & 3;
#pragma unroll
    for (int im = 0; im < 2; im++) {
        int m0 = bm + warp_m * 32 + im * 16 + rw;
#pragma unroll
        for (int jf = 0; jf < 8; jf++) {
            int n = bn + warp_n * 64 + jf * 8 + cq * 2;
            float b0 = bdx[n] + bout[n], b1 = bdx[n + 1] + bout[n + 1];
            float* a4 = acc[im][jf];
            *(float2*)(out + (size_t)m0 * DOUT + n) =
                make_float2(0.5f * (a4[0] + b0), 0.5f * (a4[1] + b1));
            *(float2*)(out + (size_t)(m0 + 8) * DOUT + n) =
                make_float2(0.5f * (a4[2] + b0), 0.5f * (a4[3] + b1));
        }
    }
}

// ---------------------------------------------------------------------------
extern "C" void kernel_launch(void* const* d_in, const int* in_sizes, int n_in,
                              void* d_out, int out_size)
{
    const float* x       = (const float*)d_in[0];
    const float* h0      = (const float*)d_in[1];
    const float* a_logit = (const float*)d_in[2];
    const float* W_dx    = (const float*)d_in[3];
    const float* b_dx    = (const float*)d_in[4];
    const float* W_in    = (const float*)d_in[5];
    const float* b_in    = (const float*)d_in[6];
    const float* W_out   = (const float*)d_in[7];
    const float* b_out   = (const float*)d_in[8];
    float* out = (float*)d_out;

    cudaFuncSetAttribute(gemm_u_mma,   cudaFuncAttributeMaxDynamicSharedMemorySize, SMEM_TOT);
    cudaFuncSetAttribute(gemm_out_mma, cudaFuncAttributeMaxDynamicSharedMemorySize, SMEM_TOT);

    prep_kernel<<<4 + 8192 + 1280, 256>>>(a_logit, x, W_in, W_dx, W_out);

    gemm_u_mma<<<dim3(DHID / 128, M_ / 128), 128, SMEM_TOT>>>(b_in);

    scan_phaseA<<<dim3(2, NCH, B_), 256>>>();
    scan_phaseC<<<dim3(2, NCH, B_), 256>>>(h0, out);

    gemm_out_mma<<<dim3(DOUT / 128, M_ / 128), 256, SMEM_TOT>>>(b_dx, b_out, out);
}